// round 1
// baseline (speedup 1.0000x reference)
#include <cuda_runtime.h>

#define NMAX 8192

// Scratch (no allocations allowed in kernel_launch).
__device__ int   g_colcount[NMAX];        // multiplicity of column c in idx_node
__device__ int   g_cntpack[2][NMAX];      // low 16: cnt, high 16: pos_cnt
__device__ float g_sumexp[2][NMAX];       // sum of exp(out[i]) over mask
__device__ float g_poslog[2][NMAX];       // sum of out[i] over mask & pos

__global__ void zero_kernel(float* out) {
    int t = blockIdx.x * blockDim.x + threadIdx.x;
    if (t < NMAX) {
        g_colcount[t] = 0;
        g_cntpack[0][t] = 0; g_cntpack[1][t] = 0;
        g_sumexp[0][t] = 0.f; g_sumexp[1][t] = 0.f;
        g_poslog[0][t] = 0.f; g_poslog[1][t] = 0.f;
    }
    if (t == 0) out[0] = 0.f;
}

__global__ void count_kernel(const int* __restrict__ idx, int K) {
    int t = blockIdx.x * blockDim.x + threadIdx.x;
    if (t < K) atomicAdd(&g_colcount[idx[t]], 1);
}

// Row-major coalesced scan of the full adjacency matrix (int4 vectorized).
// Hits (nonzero & selected column & off-diagonal) scatter into per-column stats.
__global__ void __launch_bounds__(256) main_kernel(
    const int4* __restrict__ adj,
    const float* __restrict__ outs,
    const int* __restrict__ tgt,
    int N)
{
    const int quadsPerRow = N >> 2;
    const long long total = (long long)N * quadsPerRow;
    const long long stride = (long long)gridDim.x * blockDim.x;

    for (long long q = (long long)blockIdx.x * blockDim.x + threadIdx.x;
         q < total; q += stride) {
        int4 v = __ldg(&adj[q]);
        if ((v.x | v.y | v.z | v.w) == 0) continue;   // 98.5% of quads

        int i = (int)(q / quadsPerRow);
        int c = ((int)(q - (long long)i * quadsPerRow)) << 2;

        float o = __ldg(&outs[i]);
        int   p = (__ldg(&tgt[i]) != 0) ? 1 : 0;
        float e = expf(o);
        int   pack = 1 + (p << 16);

        #pragma unroll
        for (int u = 0; u < 4; u++) {
            int val = (u == 0) ? v.x : (u == 1) ? v.y : (u == 2) ? v.z : v.w;
            int cc = c + u;
            if (val != 0 && cc != i && g_colcount[cc] > 0) {
                int side = (i < cc) ? 0 : 1;   // 0 = lower (i < k), 1 = upper (i >= k)
                atomicAdd(&g_cntpack[side][cc], pack);
                atomicAdd(&g_sumexp[side][cc], e);
                if (p) atomicAdd(&g_poslog[side][cc], o);
            }
        }
    }
}

__global__ void finalize_kernel(float* __restrict__ out, int N) {
    __shared__ float red[256];
    float local = 0.f;
    for (int c = threadIdx.x; c < N; c += blockDim.x) {
        int m = g_colcount[c];
        if (m == 0) continue;
        #pragma unroll
        for (int s = 0; s < 2; s++) {
            int pack = g_cntpack[s][c];
            int cnt = pack & 0xFFFF;
            int pc  = pack >> 16;
            if (cnt > 0 && pc == 1) {
                local += (float)m * (logf(g_sumexp[s][c]) - g_poslog[s][c]) / (float)cnt;
            }
        }
    }
    red[threadIdx.x] = local;
    __syncthreads();
    for (int s = 128; s > 0; s >>= 1) {
        if (threadIdx.x < s) red[threadIdx.x] += red[threadIdx.x + s];
        __syncthreads();
    }
    if (threadIdx.x == 0) out[0] = red[0];
}

extern "C" void kernel_launch(void* const* d_in, const int* in_sizes, int n_in,
                              void* d_out, int out_size) {
    const float* outs = (const float*)d_in[0];   // outputs  [N] f32
    const int*   tgt  = (const int*)d_in[1];     // targets  [N] i32
    const int*   adj  = (const int*)d_in[2];     // node_adj [N,N] i32
    const int*   idx  = (const int*)d_in[3];     // idx_node [K] i32
    int N = in_sizes[0];
    int K = in_sizes[3];

    float* out = (float*)d_out;

    zero_kernel<<<(NMAX + 255) / 256, 256>>>(out);
    count_kernel<<<(K + 255) / 256, 256>>>(idx, K);

    // 148 SMs * 16 blocks -> ~28 int4 quads per thread over the 256 MB matrix
    main_kernel<<<2368, 256>>>((const int4*)adj, outs, tgt, N);

    finalize_kernel<<<1, 256>>>(out, N);
}

// round 3
// speedup vs baseline: 1.8728x; 1.8728x over previous
#include <cuda_runtime.h>

#define NMAX 8192

// Scratch (no allocations allowed in kernel_launch).
__device__ int   g_colcount[NMAX];        // multiplicity of column c in idx_node
__device__ int   g_cntpack[2][NMAX];      // low 16: cnt, high 16: pos_cnt
__device__ float g_sumexp[2][NMAX];       // sum of exp(out[i]) over mask
__device__ float g_poslog[2][NMAX];       // sum of out[i] over mask & pos

__global__ void zero_kernel(float* out) {
    int t = blockIdx.x * blockDim.x + threadIdx.x;
    if (t < NMAX) {
        g_colcount[t] = 0;
        g_cntpack[0][t] = 0; g_cntpack[1][t] = 0;
        g_sumexp[0][t] = 0.f; g_sumexp[1][t] = 0.f;
        g_poslog[0][t] = 0.f; g_poslog[1][t] = 0.f;
    }
    if (t == 0) out[0] = 0.f;
}

__global__ void count_kernel(const int* __restrict__ idx, int K) {
    int t = blockIdx.x * blockDim.x + threadIdx.x;
    if (t < K) atomicAdd(&g_colcount[idx[t]], 1);
}

// Row-major coalesced scan of the full adjacency matrix (int4 vectorized).
// Hits (nonzero & selected column & off-diagonal) scatter into per-column stats.
__global__ void __launch_bounds__(256) main_kernel(
    const int4* __restrict__ adj,
    const float* __restrict__ outs,
    const int* __restrict__ tgt,
    int N, int rowShift)
{
    const int quadsPerRow = N >> 2;
    const long long total = (long long)N * quadsPerRow;
    const long long stride = (long long)gridDim.x * blockDim.x;

    for (long long q = (long long)blockIdx.x * blockDim.x + threadIdx.x;
         q < total; q += stride) {
        int4 v = __ldg(&adj[q]);
        if ((v.x | v.y | v.z | v.w) == 0) continue;   // ~98.5% of quads

        int i = (int)(q >> rowShift);                           // row index
        int c = ((int)(q - ((long long)i << rowShift))) << 2;   // first column of quad

        float o = __ldg(&outs[i]);
        int   p = (__ldg(&tgt[i]) != 0) ? 1 : 0;
        float e = expf(o);
        int   pack = 1 + (p << 16);

        #pragma unroll
        for (int u = 0; u < 4; u++) {
            int val = (u == 0) ? v.x : (u == 1) ? v.y : (u == 2) ? v.z : v.w;
            int cc = c + u;
            if (val != 0 && cc != i && __ldg(&((const int*)g_colcount)[cc]) > 0) {
                int side = (i < cc) ? 0 : 1;   // 0 = lower (i < k), 1 = upper (i >= k)
                atomicAdd(&g_cntpack[side][cc], pack);
                atomicAdd(&g_sumexp[side][cc], e);
                if (p) atomicAdd(&g_poslog[side][cc], o);
            }
        }
    }
}

// One thread per column; all loads independent; warp-reduce then one atomic per warp.
__global__ void __launch_bounds__(256) finalize_kernel(float* __restrict__ out, int N) {
    int c = blockIdx.x * blockDim.x + threadIdx.x;
    float local = 0.f;
    if (c < N) {
        int m = g_colcount[c];
        if (m != 0) {
            int pack0 = g_cntpack[0][c];
            int pack1 = g_cntpack[1][c];
            float se0 = g_sumexp[0][c], se1 = g_sumexp[1][c];
            float pl0 = g_poslog[0][c], pl1 = g_poslog[1][c];
            int cnt0 = pack0 & 0xFFFF, pc0 = pack0 >> 16;
            int cnt1 = pack1 & 0xFFFF, pc1 = pack1 >> 16;
            if (cnt0 > 0 && pc0 == 1)
                local += (float)m * (logf(se0) - pl0) / (float)cnt0;
            if (cnt1 > 0 && pc1 == 1)
                local += (float)m * (logf(se1) - pl1) / (float)cnt1;
        }
    }
    // warp reduction
    #pragma unroll
    for (int s = 16; s > 0; s >>= 1)
        local += __shfl_xor_sync(0xFFFFFFFF, local, s);
    if ((threadIdx.x & 31) == 0 && local != 0.f)
        atomicAdd(out, local);
}

extern "C" void kernel_launch(void* const* d_in, const int* in_sizes, int n_in,
                              void* d_out, int out_size) {
    const float* outs = (const float*)d_in[0];   // outputs  [N] f32
    const int*   tgt  = (const int*)d_in[1];     // targets  [N] i32
    const int*   adj  = (const int*)d_in[2];     // node_adj [N,N] i32
    const int*   idx  = (const int*)d_in[3];     // idx_node [K] i32
    int N = in_sizes[0];
    int K = in_sizes[3];

    float* out = (float*)d_out;

    // quadsPerRow = N/4 is a power of two; rowShift = log2(N/4)
    int rowShift = 0;
    for (int t = N >> 2; t > 1; t >>= 1) rowShift++;

    zero_kernel<<<(NMAX + 255) / 256, 256>>>(out);
    count_kernel<<<(K + 255) / 256, 256>>>(idx, K);

    // 148 SMs * 16 blocks -> ~28 int4 quads per thread over the 256 MB matrix
    main_kernel<<<2368, 256>>>((const int4*)adj, outs, tgt, N, rowShift);

    finalize_kernel<<<(N + 255) / 256, 256>>>(out, N);
}